// round 8
// baseline (speedup 1.0000x reference)
#include <cuda_runtime.h>

// Problem constants (fixed by the dataset)
#define B_   4096
#define H_   256
#define R_   14              // rows per CTA
#define NCTA 293             // ceil(4096/14)

typedef unsigned long long u64;

// ---------------------------------------------------------------------------
// Device scratch (no dynamic allocation allowed)
// ---------------------------------------------------------------------------
__device__ float4 g_packWhh[256 * 256];  // [k][j] -> (wi,wf,wg,wo): pairs (wi,wf)|(wg,wo)
__device__ float4 g_packWih[3 * 256];    // [e][j] same gate packing
__device__ float4 g_packBias[256];       // [j] (bi,bf,bg,bo)
__device__ float2 g_W2P[256 * 256];      // [k][j] -> (W2_h[j][k], W2_c[j][k])
__device__ float2 g_Wo1D[256 * 128];     // [k][j2] -> (w,w) duplicated
__device__ float  g_W1T[7 * 256];        // [k][j]

// ---------------------------------------------------------------------------
// Prep kernel
// ---------------------------------------------------------------------------
__global__ void prep_kernel(const float* __restrict__ W1,
                            const float* __restrict__ W2,
                            const float* __restrict__ Wih,
                            const float* __restrict__ Whh,
                            const float* __restrict__ bih,
                            const float* __restrict__ bhh,
                            const float* __restrict__ Wo1)
{
    int k = blockIdx.x;    // 0..255
    int j = threadIdx.x;   // 0..255

    g_packWhh[k * 256 + j] = make_float4(Whh[(0   + j) * 256 + k],
                                         Whh[(256 + j) * 256 + k],
                                         Whh[(512 + j) * 256 + k],
                                         Whh[(768 + j) * 256 + k]);
    g_W2P[k * 256 + j] = make_float2(W2[j * 256 + k], W2[(256 + j) * 256 + k]);
    if (j < 128) {
        float w = Wo1[j * 256 + k];
        g_Wo1D[k * 128 + j] = make_float2(w, w);
    }
    if (k < 7)   g_W1T[k * 256 + j] = W1[j * 7 + k];
    if (k < 3)   g_packWih[k * 256 + j] = make_float4(Wih[(0   + j) * 3 + k],
                                                      Wih[(256 + j) * 3 + k],
                                                      Wih[(512 + j) * 3 + k],
                                                      Wih[(768 + j) * 3 + k]);
    if (k == 0)  g_packBias[j] = make_float4(bih[0   + j] + bhh[0   + j],
                                             bih[256 + j] + bhh[256 + j],
                                             bih[512 + j] + bhh[512 + j],
                                             bih[768 + j] + bhh[768 + j]);
}

// ---------------------------------------------------------------------------
// Packed f32x2 helpers
// ---------------------------------------------------------------------------
__device__ __forceinline__ u64 fma2(u64 a, u64 b, u64 c) {
    u64 d;
    asm("fma.rn.f32x2 %0, %1, %2, %3;" : "=l"(d) : "l"(a), "l"(b), "l"(c));
    return d;
}
__device__ __forceinline__ u64 pk(float lo, float hi) {
    u64 d;
    asm("mov.b64 %0, {%1, %2};" : "=l"(d)
        : "r"(__float_as_uint(lo)), "r"(__float_as_uint(hi)));
    return d;
}
__device__ __forceinline__ float2 unpk(u64 a) {
    unsigned lo, hi;
    asm("mov.b64 {%0, %1}, %2;" : "=r"(lo), "=r"(hi) : "l"(a));
    return make_float2(__uint_as_float(lo), __uint_as_float(hi));
}

union F4 { float4 f; u64 u[2]; };
union F2 { float2 f; u64 u; };

__device__ __forceinline__ float sigmoidf_(float x) {
    return __fdividef(1.f, 1.f + __expf(-x));
}
__device__ __forceinline__ float tanhf_(float x) {
    float e = __expf(2.f * x);
    return 1.f - __fdividef(2.f, e + 1.f);
}

// Shared-memory layout (float offsets). h stored DUPLICATED (h,h) per row for the
// gate-pair GEMM, plus a PLAIN copy for the decoder.
#define OFF_HD   0                       // [256][28]: 14 dup pairs per k (112B row)
#define OFF_HP   7168                    // [256][16]: plain h, 14 used (64B row)
#define OFF_ZB   (7168 + 4096)           // [14][132]
#define OFF_XS   (OFF_ZB + 1848)         // [3][32]: 16 dup pairs per e (128B row)
#define OFF_MET  (OFF_XS + 96)           // [14][8]
#define OFF_WO2  (OFF_MET + 112)         // [3][128]
#define OFF_BO1D (OFF_WO2 + 384)         // [128] float2 (dup)
#define OFF_BO2  (OFF_BO1D + 256)        // [4]
#define SMEM_FLOATS (OFF_BO2 + 4)
#define SMEM_BYTES  (SMEM_FLOATS * 4)

// One k-slice of the gate-pair MAC: 7 broadcast LDS.128 + 28 FFMA2, zero MOVs.
__device__ __forceinline__ void mac_k(const float* __restrict__ hb, F4 w,
                                      u64* __restrict__ aif, u64* __restrict__ ago)
{
    #pragma unroll
    for (int i = 0; i < 7; i++) {
        F4 h; h.f = *reinterpret_cast<const float4*>(hb + 4 * i); // rows 2i,2i+1 dup
        aif[2 * i]     = fma2(h.u[0], w.u[0], aif[2 * i]);
        ago[2 * i]     = fma2(h.u[0], w.u[1], ago[2 * i]);
        aif[2 * i + 1] = fma2(h.u[1], w.u[0], aif[2 * i + 1]);
        ago[2 * i + 1] = fma2(h.u[1], w.u[1], ago[2 * i + 1]);
    }
}

// ---------------------------------------------------------------------------
// Main persistent kernel: one CTA handles 14 batch rows end-to-end.
// Thread t owns hidden unit j=t; accumulators pack (i,f) and (g,o) per row.
// ---------------------------------------------------------------------------
__global__ void __launch_bounds__(256, 2)
lstm_kernel(const float* __restrict__ meta,
            const float* __restrict__ b1,
            const float* __restrict__ b2,
            const float* __restrict__ bo1,
            const float* __restrict__ Wo2,
            const float* __restrict__ bo2,
            float* __restrict__ out,
            int T_eff)
{
    extern __shared__ float sm[];
    float* hd   = sm + OFF_HD;    // duplicated h
    float* hp   = sm + OFF_HP;    // plain h
    float* zbp  = sm + OFF_ZB;
    float* xsd  = sm + OFF_XS;
    float* mets = sm + OFF_MET;
    float* wo2s = sm + OFF_WO2;
    float2* bo1d = reinterpret_cast<float2*>(sm + OFF_BO1D);
    float* bo2s = sm + OFF_BO2;

    const int t    = threadIdx.x;
    const int row0 = blockIdx.x * R_;

    // ---- stage small tensors (row indices clamped for the partial last CTA) ----
    if (t < 112) {
        int r = t >> 3, e = t & 7;
        int g = row0 + r; if (g > B_ - 1) g = B_ - 1;
        mets[r * 8 + e] = (e < 7) ? meta[g * 7 + e] : 0.f;
    }
    if (t < 128) { float v = bo1[t]; bo1d[t] = make_float2(v, v); }
    wo2s[t] = Wo2[t];
    if (t < 128) wo2s[256 + t] = Wo2[256 + t];
    if (t < 3)   bo2s[t] = bo2[t];
    if (t < 42) {
        int r = t / 3, o = t - 3 * (t / 3);
        int g = row0 + r; if (g > B_ - 1) g = B_ - 1;
        float v = meta[g * 7 + o];                 // x0 = metadata[:, :3]
        *reinterpret_cast<float2*>(xsd + o * 32 + 2 * r) = make_float2(v, v);
    }
    __syncthreads();

    // ---- encoder layer 1: enc1 -> hd[t][r] duplicated ----
    {
        float a[R_];
        float bb = b1[t];
        #pragma unroll
        for (int r = 0; r < R_; r++) a[r] = bb;
        #pragma unroll
        for (int k = 0; k < 7; k++) {
            float w = g_W1T[k * 256 + t];
            #pragma unroll
            for (int r = 0; r < R_; r++) a[r] += mets[r * 8 + k] * w;
        }
        float* hrow = hd + t * 28;
        #pragma unroll
        for (int r = 0; r < R_; r++) {
            float v = fmaxf(a[r], 0.f);
            *reinterpret_cast<float2*>(hrow + 2 * r) = make_float2(v, v);
        }
    }
    __syncthreads();

    // ---- encoder layer 2: accumulate (h0, c0) pairs per row ----
    float c[R_];
    {
        u64 acc[R_];
        u64 binit = pk(b2[t], b2[256 + t]);
        #pragma unroll
        for (int r = 0; r < R_; r++) acc[r] = binit;
        const float2* w2p = g_W2P + t;
        #pragma unroll 4
        for (int k = 0; k < 256; k++) {
            F2 w; w.f = w2p[k * 256];
            const float* hb = hd + k * 28;
            #pragma unroll
            for (int i = 0; i < 7; i++) {
                F4 h; h.f = *reinterpret_cast<const float4*>(hb + 4 * i);
                acc[2 * i]     = fma2(h.u[0], w.u, acc[2 * i]);
                acc[2 * i + 1] = fma2(h.u[1], w.u, acc[2 * i + 1]);
            }
        }
        __syncthreads();   // all reads of enc1 done before overwriting hd
        float* hrow = hd + t * 28;
        #pragma unroll
        for (int r = 0; r < R_; r++) {
            float2 hc = unpk(acc[r]);        // (h0, c0)
            float hv = fmaxf(hc.x, 0.f);
            c[r] = fmaxf(hc.y, 0.f);
            *reinterpret_cast<float2*>(hrow + 2 * r) = make_float2(hv, hv);
        }
    }
    __syncthreads();

    const int j2 = t & 127;
    const int hi = t >> 7;
    float* outp = out + (long)row0 * (T_eff * 3);

    // =====================  LSTM scan  =====================
    for (int step = 0; step < T_eff; step++) {

        // ---- gate accumulation: (i,f)|(g,o) pairs per row ----
        u64 aif[R_], ago[R_];
        {
            F4 bb; bb.f = g_packBias[t];
            #pragma unroll
            for (int r = 0; r < R_; r++) { aif[r] = bb.u[0]; ago[r] = bb.u[1]; }
            #pragma unroll
            for (int e = 0; e < 3; e++) {
                F4 we; we.f = g_packWih[e * 256 + t];
                const float* xb = xsd + e * 32;
                #pragma unroll
                for (int i = 0; i < 7; i++) {
                    F4 x; x.f = *reinterpret_cast<const float4*>(xb + 4 * i);
                    aif[2 * i]     = fma2(x.u[0], we.u[0], aif[2 * i]);
                    ago[2 * i]     = fma2(x.u[0], we.u[1], ago[2 * i]);
                    aif[2 * i + 1] = fma2(x.u[1], we.u[0], aif[2 * i + 1]);
                    ago[2 * i + 1] = fma2(x.u[1], we.u[1], ago[2 * i + 1]);
                }
            }
        }
        {
            // k-blocks of 4 with front-batched weight LDG.128s (MLP=4/warp)
            const float4* wp = g_packWhh + t;
            #pragma unroll 1
            for (int kb = 0; kb < 256; kb += 4) {
                F4 w0, w1, w2, w3;
                w0.f = wp[(kb + 0) * 256];
                w1.f = wp[(kb + 1) * 256];
                w2.f = wp[(kb + 2) * 256];
                w3.f = wp[(kb + 3) * 256];
                const float* hb = hd + kb * 28;
                mac_k(hb,          w0, aif, ago);
                mac_k(hb + 28,     w1, aif, ago);
                mac_k(hb + 56,     w2, aif, ago);
                mac_k(hb + 84,     w3, aif, ago);
            }
        }
        __syncthreads();   // S0: all threads done reading hd (old h)

        // ---- elementwise LSTM cell; write new h (dup + plain) ----
        {
            float hn[R_];
            #pragma unroll
            for (int r = 0; r < R_; r++) {
                float2 ifv = unpk(aif[r]);   // (i, f)
                float2 gov = unpk(ago[r]);   // (g, o)
                float cn = sigmoidf_(ifv.y) * c[r] + sigmoidf_(ifv.x) * tanhf_(gov.x);
                hn[r] = sigmoidf_(gov.y) * tanhf_(cn);
                c[r] = cn;
            }
            float* hrow = hd + t * 28;
            #pragma unroll
            for (int r = 0; r < R_; r += 2)
                *reinterpret_cast<float4*>(hrow + 2 * r) =
                    make_float4(hn[r], hn[r], hn[r + 1], hn[r + 1]);
            float* prow = hp + t * 16;
            *reinterpret_cast<float4*>(prow + 0) = make_float4(hn[0], hn[1], hn[2], hn[3]);
            *reinterpret_cast<float4*>(prow + 4) = make_float4(hn[4], hn[5], hn[6], hn[7]);
            *reinterpret_cast<float4*>(prow + 8) = make_float4(hn[8], hn[9], hn[10], hn[11]);
            *reinterpret_cast<float2*>(prow + 12) = make_float2(hn[12], hn[13]);
        }
        __syncthreads();   // S1: new h visible

        // ---- decoder layer 1 (all 256 threads): z = relu(h . Wo1^T + bo1) ----
        {
            const float2* wo = g_Wo1D + j2;
            F2 bz; bz.f = bo1d[j2];
            if (hi == 0) {
                u64 z0 = bz.u, z1 = bz.u, z2 = bz.u, z3 = bz.u;   // rows 0..7
                #pragma unroll 1
                for (int kb = 0; kb < 256; kb += 8) {
                    F2 w[8];
                    #pragma unroll
                    for (int i = 0; i < 8; i++) w[i].f = wo[(kb + i) * 128];
                    #pragma unroll
                    for (int i = 0; i < 8; i++) {
                        const float* hb = hp + (kb + i) * 16;
                        F4 a; a.f = *reinterpret_cast<const float4*>(hb);
                        F4 b; b.f = *reinterpret_cast<const float4*>(hb + 4);
                        z0 = fma2(a.u[0], w[i].u, z0);
                        z1 = fma2(a.u[1], w[i].u, z1);
                        z2 = fma2(b.u[0], w[i].u, z2);
                        z3 = fma2(b.u[1], w[i].u, z3);
                    }
                }
                float2 v;
                v = unpk(z0); zbp[0 * 132 + j2] = fmaxf(v.x, 0.f); zbp[1 * 132 + j2] = fmaxf(v.y, 0.f);
                v = unpk(z1); zbp[2 * 132 + j2] = fmaxf(v.x, 0.f); zbp[3 * 132 + j2] = fmaxf(v.y, 0.f);
                v = unpk(z2); zbp[4 * 132 + j2] = fmaxf(v.x, 0.f); zbp[5 * 132 + j2] = fmaxf(v.y, 0.f);
                v = unpk(z3); zbp[6 * 132 + j2] = fmaxf(v.x, 0.f); zbp[7 * 132 + j2] = fmaxf(v.y, 0.f);
            } else {
                u64 z0 = bz.u, z1 = bz.u, z2 = bz.u;              // rows 8..13
                #pragma unroll 1
                for (int kb = 0; kb < 256; kb += 8) {
                    F2 w[8];
                    #pragma unroll
                    for (int i = 0; i < 8; i++) w[i].f = wo[(kb + i) * 128];
                    #pragma unroll
                    for (int i = 0; i < 8; i++) {
                        const float* hb = hp + (kb + i) * 16;
                        F4 a; a.f = *reinterpret_cast<const float4*>(hb + 8);
                        F2 cc; cc.f = *reinterpret_cast<const float2*>(hb + 12);
                        z0 = fma2(a.u[0], w[i].u, z0);
                        z1 = fma2(a.u[1], w[i].u, z1);
                        z2 = fma2(cc.u,   w[i].u, z2);
                    }
                }
                float2 v;
                v = unpk(z0); zbp[ 8 * 132 + j2] = fmaxf(v.x, 0.f); zbp[ 9 * 132 + j2] = fmaxf(v.y, 0.f);
                v = unpk(z1); zbp[10 * 132 + j2] = fmaxf(v.x, 0.f); zbp[11 * 132 + j2] = fmaxf(v.y, 0.f);
                v = unpk(z2); zbp[12 * 132 + j2] = fmaxf(v.x, 0.f); zbp[13 * 132 + j2] = fmaxf(v.y, 0.f);
            }
        }
        __syncthreads();   // S2: zb ready

        // ---- decoder layer 2: y = z . Wo2^T + bo2 ; feed back as next x ----
        if (t < 42) {
            int r = t / 3, o = t - 3 * (t / 3);
            const float* zr = zbp + r * 132;
            const float* w2 = wo2s + o * 128;
            float4 acc4 = make_float4(0.f, 0.f, 0.f, 0.f);
            #pragma unroll 8
            for (int j = 0; j < 128; j += 4) {
                float4 zv = *reinterpret_cast<const float4*>(zr + j);
                float4 wv = *reinterpret_cast<const float4*>(w2 + j);
                acc4.x += zv.x * wv.x;
                acc4.y += zv.y * wv.y;
                acc4.z += zv.z * wv.z;
                acc4.w += zv.w * wv.w;
            }
            float acc = bo2s[o] + ((acc4.x + acc4.y) + (acc4.z + acc4.w));
            if (row0 + r < B_) outp[r * (T_eff * 3) + step * 3 + o] = acc;
            *reinterpret_cast<float2*>(xsd + o * 32 + 2 * r) = make_float2(acc, acc);
        }
        __syncthreads();   // S3: xs ready for next step
    }
}

// ---------------------------------------------------------------------------
// Launch
// ---------------------------------------------------------------------------
extern "C" void kernel_launch(void* const* d_in, const int* in_sizes, int n_in,
                              void* d_out, int out_size)
{
    const float* meta = (const float*)d_in[0];
    // d_in[1] = target_seq_len (encoded by the output shape)
    const float* W1   = (const float*)d_in[2];
    const float* b1   = (const float*)d_in[3];
    const float* W2   = (const float*)d_in[4];
    const float* b2   = (const float*)d_in[5];
    const float* Wih  = (const float*)d_in[6];
    const float* Whh  = (const float*)d_in[7];
    const float* bih  = (const float*)d_in[8];
    const float* bhh  = (const float*)d_in[9];
    const float* Wo1  = (const float*)d_in[10];
    const float* bo1  = (const float*)d_in[11];
    const float* Wo2  = (const float*)d_in[12];
    const float* bo2  = (const float*)d_in[13];
    float* out = (float*)d_out;

    int T_eff = out_size / (B_ * 3);   // equals target_seq_len by output shape

    cudaFuncSetAttribute(lstm_kernel,
                         cudaFuncAttributeMaxDynamicSharedMemorySize, SMEM_BYTES);

    prep_kernel<<<256, 256>>>(W1, W2, Wih, Whh, bih, bhh, Wo1);
    lstm_kernel<<<NCTA, 256, SMEM_BYTES>>>(meta, b1, b2, bo1, Wo2, bo2, out, T_eff);
}

// round 9
// speedup vs baseline: 1.2443x; 1.2443x over previous
#include <cuda_runtime.h>

// Problem constants (fixed by the dataset)
#define B_   4096
#define H_   256
#define R_   14              // rows per CTA
#define NCTA 293             // ceil(4096/14)
#define HS   18              // h2 row stride in floats (72B, 8B-aligned u64 reads)

// ---------------------------------------------------------------------------
// Device scratch (no dynamic allocation allowed)
// ---------------------------------------------------------------------------
__device__ float4 g_packWhh[256 * 256];  // [k][j] -> (Whh_i, Whh_f, Whh_g, Whh_o)[j][k]
__device__ float4 g_packWih[3 * 256];    // [e][j]
__device__ float4 g_packBias[256];       // [j]    -> bih+bhh per gate
__device__ float  g_W2T[256 * 512];      // [k][j]
__device__ float  g_Wo1T[256 * 128];     // [k][j2]
__device__ float  g_W1T[7 * 256];        // [k][j]

// ---------------------------------------------------------------------------
// Prep kernel: transpose / gate-pack weights for coalesced LDG.128 streaming
// ---------------------------------------------------------------------------
__global__ void prep_kernel(const float* __restrict__ W1,
                            const float* __restrict__ W2,
                            const float* __restrict__ Wih,
                            const float* __restrict__ Whh,
                            const float* __restrict__ bih,
                            const float* __restrict__ bhh,
                            const float* __restrict__ Wo1)
{
    int k = blockIdx.x;    // 0..255
    int j = threadIdx.x;   // 0..255

    g_packWhh[k * 256 + j] = make_float4(Whh[(0   + j) * 256 + k],
                                         Whh[(256 + j) * 256 + k],
                                         Whh[(512 + j) * 256 + k],
                                         Whh[(768 + j) * 256 + k]);
    g_W2T[k * 512 + j]       = W2[(0   + j) * 256 + k];
    g_W2T[k * 512 + 256 + j] = W2[(256 + j) * 256 + k];
    if (j < 128) g_Wo1T[k * 128 + j] = Wo1[j * 256 + k];
    if (k < 7)   g_W1T[k * 256 + j] = W1[j * 7 + k];
    if (k < 3)   g_packWih[k * 256 + j] = make_float4(Wih[(0   + j) * 3 + k],
                                                      Wih[(256 + j) * 3 + k],
                                                      Wih[(512 + j) * 3 + k],
                                                      Wih[(768 + j) * 3 + k]);
    if (k == 0)  g_packBias[j] = make_float4(bih[0   + j] + bhh[0   + j],
                                             bih[256 + j] + bhh[256 + j],
                                             bih[512 + j] + bhh[512 + j],
                                             bih[768 + j] + bhh[768 + j]);
}

// ---------------------------------------------------------------------------
// Packed f32x2 helpers (sm_100+): doubles fp32 FMA throughput per issue
// ---------------------------------------------------------------------------
typedef unsigned long long u64;

__device__ __forceinline__ u64 fma2(u64 a, u64 b, u64 c) {
    u64 d;
    asm("fma.rn.f32x2 %0, %1, %2, %3;" : "=l"(d) : "l"(a), "l"(b), "l"(c));
    return d;
}
__device__ __forceinline__ u64 dup2(float x) {
    u64 d; unsigned xi = __float_as_uint(x);
    asm("mov.b64 %0, {%1, %2};" : "=l"(d) : "r"(xi), "r"(xi));
    return d;
}
__device__ __forceinline__ u64 pk(float lo, float hi) {
    u64 d;
    asm("mov.b64 %0, {%1, %2};" : "=l"(d)
        : "r"(__float_as_uint(lo)), "r"(__float_as_uint(hi)));
    return d;
}
__device__ __forceinline__ float2 unpk(u64 a) {
    unsigned lo, hi;
    asm("mov.b64 {%0, %1}, %2;" : "=r"(lo), "=r"(hi) : "l"(a));
    return make_float2(__uint_as_float(lo), __uint_as_float(hi));
}

__device__ __forceinline__ float sigmoidf_(float x) {
    return __fdividef(1.f, 1.f + __expf(-x));
}
// branch-free accurate tanh: 1 - 2/(e^{2x}+1); inf-safe, ~1e-6 err
__device__ __forceinline__ float tanhf_(float x) {
    float e = __expf(2.f * x);
    return 1.f - __fdividef(2.f, e + 1.f);
}

// One k-slice of the 4-gate MAC: 4 dups + 7 h loads + 28 fma2
__device__ __forceinline__ void mac_k(const float4 w, const float* __restrict__ hb,
                                      u64* ai, u64* af, u64* ag, u64* ao)
{
    u64 wx = dup2(w.x), wy = dup2(w.y), wz = dup2(w.z), ww = dup2(w.w);
    #pragma unroll
    for (int p = 0; p < 7; p++) {
        u64 h = *reinterpret_cast<const u64*>(hb + 2 * p);
        ai[p] = fma2(h, wx, ai[p]);
        af[p] = fma2(h, wy, af[p]);
        ag[p] = fma2(h, wz, ag[p]);
        ao[p] = fma2(h, ww, ao[p]);
    }
}

// ---------------------------------------------------------------------------
// Main persistent kernel: one CTA handles 14 batch rows end-to-end.
// ---------------------------------------------------------------------------
__global__ void __launch_bounds__(256, 2)
lstm_kernel(const float* __restrict__ meta,
            const float* __restrict__ b1,
            const float* __restrict__ b2,
            const float* __restrict__ bo1,
            const float* __restrict__ Wo2,
            const float* __restrict__ bo2,
            float* __restrict__ out,
            int T_eff)
{
    __shared__ __align__(16) float h2[2][256][HS]; // double-buffered h [buf][k][row]
    __shared__ __align__(16) float xs[3][16];      // [elem][row] current x (fed-back y)
    __shared__ __align__(16) float zb[14][132];    // decoder hidden [row][j2]
    __shared__ float metas[14][8];
    __shared__ __align__(16) float wo2s[3 * 128];
    __shared__ float bo1s[128];
    __shared__ float bo2s[4];

    const int t    = threadIdx.x;
    const int row0 = blockIdx.x * R_;

    // ---- stage small tensors (row indices clamped for the partial last CTA) ----
    if (t < 112) {
        int r = t >> 3, e = t & 7;
        int g = row0 + r; if (g > B_ - 1) g = B_ - 1;
        metas[r][e] = (e < 7) ? meta[g * 7 + e] : 0.f;
    }
    if (t < 128) bo1s[t] = bo1[t];
    wo2s[t] = Wo2[t];
    if (t < 128) wo2s[256 + t] = Wo2[256 + t];
    if (t < 3)   bo2s[t] = bo2[t];
    if (t < 42) {
        int r = t / 3, o = t - 3 * (t / 3);
        int g = row0 + r; if (g > B_ - 1) g = B_ - 1;
        xs[o][r] = meta[g * 7 + o];   // x0 = metadata[:, :3]
    }
    __syncthreads();

    // ---- encoder layer 1: enc1 -> h2[1][t][r] ----
    {
        float a[R_];
        float bb = b1[t];
        #pragma unroll
        for (int r = 0; r < R_; r++) a[r] = bb;
        #pragma unroll
        for (int k = 0; k < 7; k++) {
            float w = g_W1T[k * 256 + t];
            #pragma unroll
            for (int r = 0; r < R_; r++) a[r] += metas[r][k] * w;
        }
        #pragma unroll
        for (int r = 0; r < R_; r++) h2[1][t][r] = fmaxf(a[r], 0.f);
    }
    __syncthreads();

    // ---- encoder layer 2: h0 -> h2[0], c0 in regs ----
    u64 c2[7];
    {
        u64 ha[7], ca[7];
        u64 bh = dup2(b2[t]), bc = dup2(b2[256 + t]);
        #pragma unroll
        for (int p = 0; p < 7; p++) { ha[p] = bh; ca[p] = bc; }
        const float* hrow = &h2[1][0][0];
        #pragma unroll 2
        for (int k = 0; k < 256; k++) {
            u64 wh = dup2(g_W2T[k * 512 + t]);
            u64 wc = dup2(g_W2T[k * 512 + 256 + t]);
            const u64* hp = reinterpret_cast<const u64*>(hrow + k * HS);
            #pragma unroll
            for (int p = 0; p < 7; p++) {
                u64 h = hp[p];
                ha[p] = fma2(h, wh, ha[p]);
                ca[p] = fma2(h, wc, ca[p]);
            }
        }
        #pragma unroll
        for (int p = 0; p < 7; p++) {
            float2 hv = unpk(ha[p]);
            float2 cv = unpk(ca[p]);
            h2[0][t][2 * p]     = fmaxf(hv.x, 0.f);
            h2[0][t][2 * p + 1] = fmaxf(hv.y, 0.f);
            c2[p] = pk(fmaxf(cv.x, 0.f), fmaxf(cv.y, 0.f));
        }
    }
    __syncthreads();

    const int j2 = t & 127;
    const int hi = t >> 7;
    const int p0 = hi ? 4 : 0;        // decoder row-pair window [p0, p0+np)
    const int np = hi ? 3 : 4;
    float* outp = out + (long)row0 * (T_eff * 3);
    int cur = 0;

    // =====================  LSTM scan  =====================
    for (int step = 0; step < T_eff; step++) {
        const int nxt = cur ^ 1;

        // ---- gate accumulation: gates[j] = bias + x.Wih + h.Whh ----
        u64 ai[7], af[7], ag[7], ao[7];
        {
            float4 bb = g_packBias[t];
            u64 bi = dup2(bb.x), bf = dup2(bb.y), bg = dup2(bb.z), bo = dup2(bb.w);
            #pragma unroll
            for (int p = 0; p < 7; p++) { ai[p] = bi; af[p] = bf; ag[p] = bg; ao[p] = bo; }
            #pragma unroll
            for (int e = 0; e < 3; e++) {
                float4 we = g_packWih[e * 256 + t];
                u64 wx = dup2(we.x), wy = dup2(we.y), wz = dup2(we.z), ww = dup2(we.w);
                #pragma unroll
                for (int p = 0; p < 7; p++) {
                    u64 xp = *reinterpret_cast<const u64*>(&xs[e][2 * p]);
                    ai[p] = fma2(xp, wx, ai[p]);
                    af[p] = fma2(xp, wy, af[p]);
                    ag[p] = fma2(xp, wz, ag[p]);
                    ao[p] = fma2(xp, ww, ao[p]);
                }
            }
        }
        {
            // k-blocks of 4, weights register-double-buffered ONE BLOCK AHEAD:
            // the FFMA2 stream of block kb covers the LDG latency of block kb+4.
            const float4* wp   = g_packWhh + t;
            const float*  hrow = &h2[cur][0][0];
            float4 w0 = wp[0 * 256];
            float4 w1 = wp[1 * 256];
            float4 w2 = wp[2 * 256];
            float4 w3 = wp[3 * 256];
            #pragma unroll 1
            for (int kb = 0; kb < 252; kb += 4) {
                float4 n0 = wp[(kb + 4) * 256];
                float4 n1 = wp[(kb + 5) * 256];
                float4 n2 = wp[(kb + 6) * 256];
                float4 n3 = wp[(kb + 7) * 256];
                const float* hb = hrow + kb * HS;
                mac_k(w0, hb,          ai, af, ag, ao);
                mac_k(w1, hb + HS,     ai, af, ag, ao);
                mac_k(w2, hb + 2 * HS, ai, af, ag, ao);
                mac_k(w3, hb + 3 * HS, ai, af, ag, ao);
                w0 = n0; w1 = n1; w2 = n2; w3 = n3;
            }
            const float* hb = hrow + 252 * HS;
            mac_k(w0, hb,          ai, af, ag, ao);
            mac_k(w1, hb + HS,     ai, af, ag, ao);
            mac_k(w2, hb + 2 * HS, ai, af, ag, ao);
            mac_k(w3, hb + 3 * HS, ai, af, ag, ao);
        }

        // ---- elementwise LSTM cell update: write new h into the OTHER buffer ----
        #pragma unroll
        for (int p = 0; p < 7; p++) {
            float2 iv = unpk(ai[p]), fv = unpk(af[p]);
            float2 gv = unpk(ag[p]), ov = unpk(ao[p]);
            float2 cv = unpk(c2[p]);
            float c0n = sigmoidf_(fv.x) * cv.x + sigmoidf_(iv.x) * tanhf_(gv.x);
            float c1n = sigmoidf_(fv.y) * cv.y + sigmoidf_(iv.y) * tanhf_(gv.y);
            h2[nxt][t][2 * p]     = sigmoidf_(ov.x) * tanhf_(c0n);
            h2[nxt][t][2 * p + 1] = sigmoidf_(ov.y) * tanhf_(c1n);
            c2[p] = pk(c0n, c1n);
        }
        __syncthreads();   // S1: new h visible; everyone done reading xs

        // ---- decoder layer 1 (ALL 256 threads): z = relu(h . Wo1^T + bo1) ----
        {
            u64 z[4];
            u64 bz = dup2(bo1s[j2]);
            #pragma unroll
            for (int p = 0; p < 4; p++) z[p] = bz;
            const float* wo    = g_Wo1T + j2;
            const float* hrow2 = &h2[nxt][0][0] + 2 * p0;
            float wv[8];
            #pragma unroll
            for (int i = 0; i < 8; i++) wv[i] = wo[i * 128];
            #pragma unroll 1
            for (int kb = 0; kb < 248; kb += 8) {
                float nv[8];
                #pragma unroll
                for (int i = 0; i < 8; i++) nv[i] = wo[(kb + 8 + i) * 128];
                #pragma unroll
                for (int i = 0; i < 8; i++) {
                    u64 wd = dup2(wv[i]);
                    const float* hb = hrow2 + (kb + i) * HS;
                    #pragma unroll
                    for (int p = 0; p < 4; p++)
                        if (p < np)
                            z[p] = fma2(*reinterpret_cast<const u64*>(hb + 2 * p), wd, z[p]);
                }
                #pragma unroll
                for (int i = 0; i < 8; i++) wv[i] = nv[i];
            }
            #pragma unroll
            for (int i = 0; i < 8; i++) {
                u64 wd = dup2(wv[i]);
                const float* hb = hrow2 + (248 + i) * HS;
                #pragma unroll
                for (int p = 0; p < 4; p++)
                    if (p < np)
                        z[p] = fma2(*reinterpret_cast<const u64*>(hb + 2 * p), wd, z[p]);
            }
            #pragma unroll
            for (int p = 0; p < 4; p++)
                if (p < np) {
                    float2 zv = unpk(z[p]);
                    zb[2 * (p0 + p)][j2]     = fmaxf(zv.x, 0.f);
                    zb[2 * (p0 + p) + 1][j2] = fmaxf(zv.y, 0.f);
                }
        }
        __syncthreads();   // S2: zb ready

        // ---- decoder layer 2: y = z . Wo2^T + bo2 ; feed back as next x ----
        if (t < 42) {
            int r = t / 3, o = t - 3 * (t / 3);
            const float* zr = zb[r];
            const float* w2 = &wo2s[o * 128];
            float4 acc4 = make_float4(0.f, 0.f, 0.f, 0.f);
            #pragma unroll 8
            for (int j = 0; j < 128; j += 4) {
                float4 zv = *reinterpret_cast<const float4*>(zr + j);
                float4 wv2 = *reinterpret_cast<const float4*>(w2 + j);
                acc4.x += zv.x * wv2.x;
                acc4.y += zv.y * wv2.y;
                acc4.z += zv.z * wv2.z;
                acc4.w += zv.w * wv2.w;
            }
            float acc = bo2s[o] + ((acc4.x + acc4.y) + (acc4.z + acc4.w));
            if (row0 + r < B_) outp[r * (T_eff * 3) + step * 3 + o] = acc;
            xs[o][r] = acc;
        }
        __syncthreads();   // S3: xs ready for next step

        cur = nxt;
    }
}

// ---------------------------------------------------------------------------
// Launch
// ---------------------------------------------------------------------------
extern "C" void kernel_launch(void* const* d_in, const int* in_sizes, int n_in,
                              void* d_out, int out_size)
{
    const float* meta = (const float*)d_in[0];
    // d_in[1] = target_seq_len (encoded by the output shape)
    const float* W1   = (const float*)d_in[2];
    const float* b1   = (const float*)d_in[3];
    const float* W2   = (const float*)d_in[4];
    const float* b2   = (const float*)d_in[5];
    const float* Wih  = (const float*)d_in[6];
    const float* Whh  = (const float*)d_in[7];
    const float* bih  = (const float*)d_in[8];
    const float* bhh  = (const float*)d_in[9];
    const float* Wo1  = (const float*)d_in[10];
    const float* bo1  = (const float*)d_in[11];
    const float* Wo2  = (const float*)d_in[12];
    const float* bo2  = (const float*)d_in[13];
    float* out = (float*)d_out;

    int T_eff = out_size / (B_ * 3);   // equals target_seq_len by output shape

    prep_kernel<<<256, 256>>>(W1, W2, Wih, Whh, bih, bhh, Wo1);
    lstm_kernel<<<NCTA, 256>>>(meta, b1, b2, bo1, Wo2, bo2, out, T_eff);
}

// round 11
// speedup vs baseline: 1.2928x; 1.0389x over previous
#include <cuda_runtime.h>

// Problem constants (fixed by the dataset)
#define B_   4096
#define H_   256
#define R_   14              // rows per CTA
#define NCTA 293             // ceil(4096/14)
#define HS   16              // h2 row stride in floats (64B, 16B-aligned for LDS.128)

// ---------------------------------------------------------------------------
// Device scratch (no dynamic allocation allowed)
// ---------------------------------------------------------------------------
__device__ float4 g_packWhh[256 * 256];  // [k][j] -> (Whh_i, Whh_f, Whh_g, Whh_o)[j][k]
__device__ float4 g_packWih[3 * 256];    // [e][j]
__device__ float4 g_packBias[256];       // [j]    -> bih+bhh per gate
__device__ float  g_W2T[256 * 512];      // [k][j]
__device__ float  g_Wo1T[256 * 128];     // [k][j2]
__device__ float  g_W1T[7 * 256];        // [k][j]

// ---------------------------------------------------------------------------
// Prep kernel: transpose / gate-pack weights for coalesced LDG.128 streaming
// ---------------------------------------------------------------------------
__global__ void prep_kernel(const float* __restrict__ W1,
                            const float* __restrict__ W2,
                            const float* __restrict__ Wih,
                            const float* __restrict__ Whh,
                            const float* __restrict__ bih,
                            const float* __restrict__ bhh,
                            const float* __restrict__ Wo1)
{
    int k = blockIdx.x;    // 0..255
    int j = threadIdx.x;   // 0..255

    g_packWhh[k * 256 + j] = make_float4(Whh[(0   + j) * 256 + k],
                                         Whh[(256 + j) * 256 + k],
                                         Whh[(512 + j) * 256 + k],
                                         Whh[(768 + j) * 256 + k]);
    g_W2T[k * 512 + j]       = W2[(0   + j) * 256 + k];
    g_W2T[k * 512 + 256 + j] = W2[(256 + j) * 256 + k];
    if (j < 128) g_Wo1T[k * 128 + j] = Wo1[j * 256 + k];
    if (k < 7)   g_W1T[k * 256 + j] = W1[j * 7 + k];
    if (k < 3)   g_packWih[k * 256 + j] = make_float4(Wih[(0   + j) * 3 + k],
                                                      Wih[(256 + j) * 3 + k],
                                                      Wih[(512 + j) * 3 + k],
                                                      Wih[(768 + j) * 3 + k]);
    if (k == 0)  g_packBias[j] = make_float4(bih[0   + j] + bhh[0   + j],
                                             bih[256 + j] + bhh[256 + j],
                                             bih[512 + j] + bhh[512 + j],
                                             bih[768 + j] + bhh[768 + j]);
}

// ---------------------------------------------------------------------------
// Packed f32x2 helpers (sm_100+): doubles fp32 FMA throughput per issue
// ---------------------------------------------------------------------------
typedef unsigned long long u64;

union F4 { float4 f; u64 u[2]; };
union F2 { float2 f; u64 u; };

__device__ __forceinline__ u64 fma2(u64 a, u64 b, u64 c) {
    u64 d;
    asm("fma.rn.f32x2 %0, %1, %2, %3;" : "=l"(d) : "l"(a), "l"(b), "l"(c));
    return d;
}
__device__ __forceinline__ u64 dup2(float x) {
    u64 d; unsigned xi = __float_as_uint(x);
    asm("mov.b64 %0, {%1, %2};" : "=l"(d) : "r"(xi), "r"(xi));
    return d;
}
__device__ __forceinline__ u64 pk(float lo, float hi) {
    u64 d;
    asm("mov.b64 %0, {%1, %2};" : "=l"(d)
        : "r"(__float_as_uint(lo)), "r"(__float_as_uint(hi)));
    return d;
}
__device__ __forceinline__ float2 unpk(u64 a) {
    unsigned lo, hi;
    asm("mov.b64 {%0, %1}, %2;" : "=r"(lo), "=r"(hi) : "l"(a));
    return make_float2(__uint_as_float(lo), __uint_as_float(hi));
}

__device__ __forceinline__ float sigmoidf_(float x) {
    return __fdividef(1.f, 1.f + __expf(-x));
}
// branch-free accurate tanh: 1 - 2/(e^{2x}+1); inf-safe, ~1e-6 err
__device__ __forceinline__ float tanhf_(float x) {
    float e = __expf(2.f * x);
    return 1.f - __fdividef(2.f, e + 1.f);
}

// One k-slice of the 4-gate MAC: 4 dup2 + 3 LDS.128 + 1 LDS.64 + 28 fma2
__device__ __forceinline__ void mac_k(const float4 w, const float* __restrict__ hb,
                                      u64* ai, u64* af, u64* ag, u64* ao)
{
    u64 wx = dup2(w.x), wy = dup2(w.y), wz = dup2(w.z), ww = dup2(w.w);
    F4 hA, hB, hC; F2 hD;
    hA.f = *reinterpret_cast<const float4*>(hb);
    hB.f = *reinterpret_cast<const float4*>(hb + 4);
    hC.f = *reinterpret_cast<const float4*>(hb + 8);
    hD.f = *reinterpret_cast<const float2*>(hb + 12);
    u64 h[7] = { hA.u[0], hA.u[1], hB.u[0], hB.u[1], hC.u[0], hC.u[1], hD.u };
    #pragma unroll
    for (int p = 0; p < 7; p++) {
        ai[p] = fma2(h[p], wx, ai[p]);
        af[p] = fma2(h[p], wy, af[p]);
        ag[p] = fma2(h[p], wz, ag[p]);
        ao[p] = fma2(h[p], ww, ao[p]);
    }
}

// ---------------------------------------------------------------------------
// Main persistent kernel: one CTA handles 14 batch rows end-to-end.
// ---------------------------------------------------------------------------
__global__ void __launch_bounds__(256, 2)
lstm_kernel(const float* __restrict__ meta,
            const float* __restrict__ b1,
            const float* __restrict__ b2,
            const float* __restrict__ bo1,
            const float* __restrict__ Wo2,
            const float* __restrict__ bo2,
            float* __restrict__ out,
            int T_eff)
{
    __shared__ __align__(16) float h2[2][256][HS]; // double-buffered h [buf][k][row]
    __shared__ __align__(16) float xs[3][16];      // [elem][row] current x (fed-back y)
    __shared__ __align__(16) float zb[14][132];    // decoder hidden [row][j2]
    __shared__ float metas[14][8];
    __shared__ __align__(16) float wo2s[3 * 128];
    __shared__ float bo1s[128];
    __shared__ float bo2s[4];

    const int t    = threadIdx.x;
    const int row0 = blockIdx.x * R_;

    // ---- stage small tensors (row indices clamped for the partial last CTA) ----
    if (t < 112) {
        int r = t >> 3, e = t & 7;
        int g = row0 + r; if (g > B_ - 1) g = B_ - 1;
        metas[r][e] = (e < 7) ? meta[g * 7 + e] : 0.f;
    }
    if (t < 128) bo1s[t] = bo1[t];
    wo2s[t] = Wo2[t];
    if (t < 128) wo2s[256 + t] = Wo2[256 + t];
    if (t < 3)   bo2s[t] = bo2[t];
    if (t < 42) {
        int r = t / 3, o = t - 3 * (t / 3);
        int g = row0 + r; if (g > B_ - 1) g = B_ - 1;
        xs[o][r] = meta[g * 7 + o];   // x0 = metadata[:, :3]
    }
    __syncthreads();

    // ---- encoder layer 1: enc1 -> h2[1][t][r] ----
    {
        float a[R_];
        float bb = b1[t];
        #pragma unroll
        for (int r = 0; r < R_; r++) a[r] = bb;
        #pragma unroll
        for (int k = 0; k < 7; k++) {
            float w = g_W1T[k * 256 + t];
            #pragma unroll
            for (int r = 0; r < R_; r++) a[r] += metas[r][k] * w;
        }
        #pragma unroll
        for (int r = 0; r < R_; r++) h2[1][t][r] = fmaxf(a[r], 0.f);
    }
    __syncthreads();

    // ---- encoder layer 2: h0 -> h2[0], c0 in regs ----
    u64 c2[7];
    {
        u64 ha[7], ca[7];
        u64 bh = dup2(b2[t]), bc = dup2(b2[256 + t]);
        #pragma unroll
        for (int p = 0; p < 7; p++) { ha[p] = bh; ca[p] = bc; }
        const float* hrow = &h2[1][0][0];
        #pragma unroll 2
        for (int k = 0; k < 256; k++) {
            u64 wh = dup2(g_W2T[k * 512 + t]);
            u64 wc = dup2(g_W2T[k * 512 + 256 + t]);
            const float* hb = hrow + k * HS;
            F4 hA, hB, hC; F2 hD;
            hA.f = *reinterpret_cast<const float4*>(hb);
            hB.f = *reinterpret_cast<const float4*>(hb + 4);
            hC.f = *reinterpret_cast<const float4*>(hb + 8);
            hD.f = *reinterpret_cast<const float2*>(hb + 12);
            u64 h[7] = { hA.u[0], hA.u[1], hB.u[0], hB.u[1], hC.u[0], hC.u[1], hD.u };
            #pragma unroll
            for (int p = 0; p < 7; p++) {
                ha[p] = fma2(h[p], wh, ha[p]);
                ca[p] = fma2(h[p], wc, ca[p]);
            }
        }
        #pragma unroll
        for (int p = 0; p < 7; p++) {
            float2 hv = unpk(ha[p]);
            float2 cv = unpk(ca[p]);
            h2[0][t][2 * p]     = fmaxf(hv.x, 0.f);
            h2[0][t][2 * p + 1] = fmaxf(hv.y, 0.f);
            c2[p] = pk(fmaxf(cv.x, 0.f), fmaxf(cv.y, 0.f));
        }
    }
    __syncthreads();

    const int j2 = t & 127;
    const int hi = t >> 7;
    float* outp = out + (long)row0 * (T_eff * 3);
    int cur = 0;

    // =====================  LSTM scan  =====================
    for (int step = 0; step < T_eff; step++) {
        const int nxt = cur ^ 1;

        // ---- gate accumulation: gates[j] = bias + x.Wih + h.Whh ----
        u64 ai[7], af[7], ag[7], ao[7];
        {
            float4 bb = g_packBias[t];
            u64 bi = dup2(bb.x), bf = dup2(bb.y), bg = dup2(bb.z), bo = dup2(bb.w);
            #pragma unroll
            for (int p = 0; p < 7; p++) { ai[p] = bi; af[p] = bf; ag[p] = bg; ao[p] = bo; }
            #pragma unroll
            for (int e = 0; e < 3; e++) {
                float4 we = g_packWih[e * 256 + t];
                u64 wx = dup2(we.x), wy = dup2(we.y), wz = dup2(we.z), ww = dup2(we.w);
                #pragma unroll
                for (int p = 0; p < 7; p++) {
                    u64 xp = *reinterpret_cast<const u64*>(&xs[e][2 * p]);
                    ai[p] = fma2(xp, wx, ai[p]);
                    af[p] = fma2(xp, wy, af[p]);
                    ag[p] = fma2(xp, wz, ag[p]);
                    ao[p] = fma2(xp, ww, ao[p]);
                }
            }
        }
        {
            // Ping-pong software pipeline (no register-copy MOVs): block A computes
            // while block B's weights are in flight, and vice versa.
            const float4* wp   = g_packWhh + t;
            const float*  hrow = &h2[cur][0][0];
            float4 a0 = wp[0 * 256], a1 = wp[1 * 256], a2 = wp[2 * 256], a3 = wp[3 * 256];
            #pragma unroll 1
            for (int kb = 0; kb < 248; kb += 8) {
                float4 b0 = wp[(kb + 4) * 256], b1 = wp[(kb + 5) * 256],
                       b2w = wp[(kb + 6) * 256], b3 = wp[(kb + 7) * 256];
                const float* hb = hrow + kb * HS;
                mac_k(a0, hb,          ai, af, ag, ao);
                mac_k(a1, hb + HS,     ai, af, ag, ao);
                mac_k(a2, hb + 2 * HS, ai, af, ag, ao);
                mac_k(a3, hb + 3 * HS, ai, af, ag, ao);
                a0 = wp[(kb + 8) * 256]; a1 = wp[(kb + 9) * 256];
                a2 = wp[(kb + 10) * 256]; a3 = wp[(kb + 11) * 256];
                mac_k(b0,  hb + 4 * HS, ai, af, ag, ao);
                mac_k(b1,  hb + 5 * HS, ai, af, ag, ao);
                mac_k(b2w, hb + 6 * HS, ai, af, ag, ao);
                mac_k(b3,  hb + 7 * HS, ai, af, ag, ao);
            }
            // epilogue: k = 248..255 (a holds 248..251, loaded in the last iteration)
            {
                float4 b0 = wp[252 * 256], b1 = wp[253 * 256],
                       b2w = wp[254 * 256], b3 = wp[255 * 256];
                const float* hb = hrow + 248 * HS;
                mac_k(a0, hb,          ai, af, ag, ao);
                mac_k(a1, hb + HS,     ai, af, ag, ao);
                mac_k(a2, hb + 2 * HS, ai, af, ag, ao);
                mac_k(a3, hb + 3 * HS, ai, af, ag, ao);
                mac_k(b0,  hb + 4 * HS, ai, af, ag, ao);
                mac_k(b1,  hb + 5 * HS, ai, af, ag, ao);
                mac_k(b2w, hb + 6 * HS, ai, af, ag, ao);
                mac_k(b3,  hb + 7 * HS, ai, af, ag, ao);
            }
        }

        // ---- elementwise LSTM cell update: write new h into the OTHER buffer ----
        {
            float hn[R_];
            #pragma unroll
            for (int p = 0; p < 7; p++) {
                float2 iv = unpk(ai[p]), fv = unpk(af[p]);
                float2 gv = unpk(ag[p]), ov = unpk(ao[p]);
                float2 cv = unpk(c2[p]);
                float c0n = sigmoidf_(fv.x) * cv.x + sigmoidf_(iv.x) * tanhf_(gv.x);
                float c1n = sigmoidf_(fv.y) * cv.y + sigmoidf_(iv.y) * tanhf_(gv.y);
                hn[2 * p]     = sigmoidf_(ov.x) * tanhf_(c0n);
                hn[2 * p + 1] = sigmoidf_(ov.y) * tanhf_(c1n);
                c2[p] = pk(c0n, c1n);
            }
            float* hrow = &h2[nxt][t][0];
            *reinterpret_cast<float4*>(hrow + 0)  = make_float4(hn[0], hn[1], hn[2], hn[3]);
            *reinterpret_cast<float4*>(hrow + 4)  = make_float4(hn[4], hn[5], hn[6], hn[7]);
            *reinterpret_cast<float4*>(hrow + 8)  = make_float4(hn[8], hn[9], hn[10], hn[11]);
            *reinterpret_cast<float2*>(hrow + 12) = make_float2(hn[12], hn[13]);
        }
        __syncthreads();   // S1: new h visible; everyone done reading xs

        // ---- decoder layer 1 (ALL 256 threads): z = relu(h . Wo1^T + bo1) ----
        {
            const float* wo    = g_Wo1T + j2;
            const float* hrow2 = &h2[nxt][0][0];
            u64 bz = dup2(bo1s[j2]);
            float wv[8];
            #pragma unroll
            for (int i = 0; i < 8; i++) wv[i] = wo[i * 128];
            if (hi == 0) {
                u64 z0 = bz, z1 = bz, z2 = bz, z3 = bz;           // rows 0..7
                #pragma unroll 1
                for (int kb = 0; kb < 248; kb += 8) {
                    float nv[8];
                    #pragma unroll
                    for (int i = 0; i < 8; i++) nv[i] = wo[(kb + 8 + i) * 128];
                    #pragma unroll
                    for (int i = 0; i < 8; i++) {
                        u64 wd = dup2(wv[i]);
                        const float* hb = hrow2 + (kb + i) * HS;
                        F4 A, Bv;
                        A.f  = *reinterpret_cast<const float4*>(hb);
                        Bv.f = *reinterpret_cast<const float4*>(hb + 4);
                        z0 = fma2(A.u[0],  wd, z0);
                        z1 = fma2(A.u[1],  wd, z1);
                        z2 = fma2(Bv.u[0], wd, z2);
                        z3 = fma2(Bv.u[1], wd, z3);
                    }
                    #pragma unroll
                    for (int i = 0; i < 8; i++) wv[i] = nv[i];
                }
                #pragma unroll
                for (int i = 0; i < 8; i++) {
                    u64 wd = dup2(wv[i]);
                    const float* hb = hrow2 + (248 + i) * HS;
                    F4 A, Bv;
                    A.f  = *reinterpret_cast<const float4*>(hb);
                    Bv.f = *reinterpret_cast<const float4*>(hb + 4);
                    z0 = fma2(A.u[0],  wd, z0);
                    z1 = fma2(A.u[1],  wd, z1);
                    z2 = fma2(Bv.u[0], wd, z2);
                    z3 = fma2(Bv.u[1], wd, z3);
                }
                float2 v;
                v = unpk(z0); zb[0][j2] = fmaxf(v.x, 0.f); zb[1][j2] = fmaxf(v.y, 0.f);
                v = unpk(z1); zb[2][j2] = fmaxf(v.x, 0.f); zb[3][j2] = fmaxf(v.y, 0.f);
                v = unpk(z2); zb[4][j2] = fmaxf(v.x, 0.f); zb[5][j2] = fmaxf(v.y, 0.f);
                v = unpk(z3); zb[6][j2] = fmaxf(v.x, 0.f); zb[7][j2] = fmaxf(v.y, 0.f);
            } else {
                u64 z0 = bz, z1 = bz, z2 = bz;                    // rows 8..13
                #pragma unroll 1
                for (int kb = 0; kb < 248; kb += 8) {
                    float nv[8];
                    #pragma unroll
                    for (int i = 0; i < 8; i++) nv[i] = wo[(kb + 8 + i) * 128];
                    #pragma unroll
                    for (int i = 0; i < 8; i++) {
                        u64 wd = dup2(wv[i]);
                        const float* hb = hrow2 + (kb + i) * HS;
                        F4 Cv; F2 Dv;
                        Cv.f = *reinterpret_cast<const float4*>(hb + 8);
                        Dv.f = *reinterpret_cast<const float2*>(hb + 12);
                        z0 = fma2(Cv.u[0], wd, z0);
                        z1 = fma2(Cv.u[1], wd, z1);
                        z2 = fma2(Dv.u,    wd, z2);
                    }
                    #pragma unroll
                    for (int i = 0; i < 8; i++) wv[i] = nv[i];
                }
                #pragma unroll
                for (int i = 0; i < 8; i++) {
                    u64 wd = dup2(wv[i]);
                    const float* hb = hrow2 + (248 + i) * HS;
                    F4 Cv; F2 Dv;
                    Cv.f = *reinterpret_cast<const float4*>(hb + 8);
                    Dv.f = *reinterpret_cast<const float2*>(hb + 12);
                    z0 = fma2(Cv.u[0], wd, z0);
                    z1 = fma2(Cv.u[1], wd, z1);
                    z2 = fma2(Dv.u,    wd, z2);
                }
                float2 v;
                v = unpk(z0); zb[ 8][j2] = fmaxf(v.x, 0.f); zb[ 9][j2] = fmaxf(v.y, 0.f);
                v = unpk(z1); zb[10][j2] = fmaxf(v.x, 0.f); zb[11][j2] = fmaxf(v.y, 0.f);
                v = unpk(z2); zb[12][j2] = fmaxf(v.x, 0.f); zb[13][j2] = fmaxf(v.y, 0.f);
            }
        }
        __syncthreads();   // S2: zb ready

        // ---- decoder layer 2: y = z . Wo2^T + bo2 ; feed back as next x ----
        if (t < 42) {
            int r = t / 3, o = t - 3 * (t / 3);
            const float* zr = zb[r];
            const float* w2 = &wo2s[o * 128];
            float4 acc4 = make_float4(0.f, 0.f, 0.f, 0.f);
            #pragma unroll 8
            for (int j = 0; j < 128; j += 4) {
                float4 zv = *reinterpret_cast<const float4*>(zr + j);
                float4 wv2 = *reinterpret_cast<const float4*>(w2 + j);
                acc4.x += zv.x * wv2.x;
                acc4.y += zv.y * wv2.y;
                acc4.z += zv.z * wv2.z;
                acc4.w += zv.w * wv2.w;
            }
            float acc = bo2s[o] + ((acc4.x + acc4.y) + (acc4.z + acc4.w));
            if (row0 + r < B_) outp[r * (T_eff * 3) + step * 3 + o] = acc;
            xs[o][r] = acc;
        }
        __syncthreads();   // S3: xs ready for next step

        cur = nxt;
    }
}

// ---------------------------------------------------------------------------
// Launch
// ---------------------------------------------------------------------------
extern "C" void kernel_launch(void* const* d_in, const int* in_sizes, int n_in,
                              void* d_out, int out_size)
{
    const float* meta = (const float*)d_in[0];
    // d_in[1] = target_seq_len (encoded by the output shape)
    const float* W1   = (const float*)d_in[2];
    const float* b1   = (const float*)d_in[3];
    const float* W2   = (const float*)d_in[4];
    const float* b2   = (const float*)d_in[5];
    const float* Wih  = (const float*)d_in[6];
    const float* Whh  = (const float*)d_in[7];
    const float* bih  = (const float*)d_in[8];
    const float* bhh  = (const float*)d_in[9];
    const float* Wo1  = (const float*)d_in[10];
    const float* bo1  = (const float*)d_in[11];
    const float* Wo2  = (const float*)d_in[12];
    const float* bo2  = (const float*)d_in[13];
    float* out = (float*)d_out;

    int T_eff = out_size / (B_ * 3);   // equals target_seq_len by output shape

    prep_kernel<<<256, 256>>>(W1, W2, Wih, Whh, bih, bhh, Wo1);
    lstm_kernel<<<NCTA, 256>>>(meta, b1, b2, bo1, Wo2, bo2, out, T_eff);
}

// round 12
// speedup vs baseline: 1.3051x; 1.0096x over previous
#include <cuda_runtime.h>

// Problem constants (fixed by the dataset)
#define B_   4096
#define H_   256
#define R_   14              // rows per CTA
#define NCTA 293             // ceil(4096/14)
#define HS   16              // h2 row stride in floats (64B, 16B-aligned for LDS.128)

// ---------------------------------------------------------------------------
// Device scratch (no dynamic allocation allowed)
// ---------------------------------------------------------------------------
__device__ float4 g_packWhh[256 * 256];  // [k][j] -> (Whh_i, Whh_f, Whh_g, Whh_o)[j][k]
__device__ float4 g_packWih[3 * 256];    // [e][j]
__device__ float4 g_packBias[256];       // [j]    -> bih+bhh per gate
__device__ float  g_W2T[256 * 512];      // [k][j]
__device__ float  g_Wo1T[256 * 128];     // [k][j2]
__device__ float  g_W1T[7 * 256];        // [k][j]

// ---------------------------------------------------------------------------
// Prep kernel: transpose / gate-pack weights for coalesced LDG.128 streaming
// ---------------------------------------------------------------------------
__global__ void prep_kernel(const float* __restrict__ W1,
                            const float* __restrict__ W2,
                            const float* __restrict__ Wih,
                            const float* __restrict__ Whh,
                            const float* __restrict__ bih,
                            const float* __restrict__ bhh,
                            const float* __restrict__ Wo1)
{
    int k = blockIdx.x;    // 0..255
    int j = threadIdx.x;   // 0..255

    g_packWhh[k * 256 + j] = make_float4(Whh[(0   + j) * 256 + k],
                                         Whh[(256 + j) * 256 + k],
                                         Whh[(512 + j) * 256 + k],
                                         Whh[(768 + j) * 256 + k]);
    g_W2T[k * 512 + j]       = W2[(0   + j) * 256 + k];
    g_W2T[k * 512 + 256 + j] = W2[(256 + j) * 256 + k];
    if (j < 128) g_Wo1T[k * 128 + j] = Wo1[j * 256 + k];
    if (k < 7)   g_W1T[k * 256 + j] = W1[j * 7 + k];
    if (k < 3)   g_packWih[k * 256 + j] = make_float4(Wih[(0   + j) * 3 + k],
                                                      Wih[(256 + j) * 3 + k],
                                                      Wih[(512 + j) * 3 + k],
                                                      Wih[(768 + j) * 3 + k]);
    if (k == 0)  g_packBias[j] = make_float4(bih[0   + j] + bhh[0   + j],
                                             bih[256 + j] + bhh[256 + j],
                                             bih[512 + j] + bhh[512 + j],
                                             bih[768 + j] + bhh[768 + j]);
}

// ---------------------------------------------------------------------------
// Packed f32x2 helpers (sm_100+): doubles fp32 FMA throughput per issue
// ---------------------------------------------------------------------------
typedef unsigned long long u64;

union F4 { float4 f; u64 u[2]; };
union F2 { float2 f; u64 u; };

__device__ __forceinline__ u64 fma2(u64 a, u64 b, u64 c) {
    u64 d;
    asm("fma.rn.f32x2 %0, %1, %2, %3;" : "=l"(d) : "l"(a), "l"(b), "l"(c));
    return d;
}
__device__ __forceinline__ u64 dup2(float x) {
    u64 d; unsigned xi = __float_as_uint(x);
    asm("mov.b64 %0, {%1, %2};" : "=l"(d) : "r"(xi), "r"(xi));
    return d;
}
__device__ __forceinline__ u64 pk(float lo, float hi) {
    u64 d;
    asm("mov.b64 %0, {%1, %2};" : "=l"(d)
        : "r"(__float_as_uint(lo)), "r"(__float_as_uint(hi)));
    return d;
}
__device__ __forceinline__ float2 unpk(u64 a) {
    unsigned lo, hi;
    asm("mov.b64 {%0, %1}, %2;" : "=r"(lo), "=r"(hi) : "l"(a));
    return make_float2(__uint_as_float(lo), __uint_as_float(hi));
}

__device__ __forceinline__ float sigmoidf_(float x) {
    return __fdividef(1.f, 1.f + __expf(-x));
}
// branch-free accurate tanh: 1 - 2/(e^{2x}+1); inf-safe, ~1e-6 err
__device__ __forceinline__ float tanhf_(float x) {
    float e = __expf(2.f * x);
    return 1.f - __fdividef(2.f, e + 1.f);
}

// h operands for one k-slice: 14 rows as 7 u64 pairs (3 LDS.128 + 1 LDS.64)
struct H7 { F4 A, B, C; F2 D; };

__device__ __forceinline__ void loadh(H7& h, const float* __restrict__ hb) {
    h.A.f = *reinterpret_cast<const float4*>(hb);
    h.B.f = *reinterpret_cast<const float4*>(hb + 4);
    h.C.f = *reinterpret_cast<const float4*>(hb + 8);
    h.D.f = *reinterpret_cast<const float2*>(hb + 12);
}

// 4-gate MAC with PRELOADED h: 4 dup2 + 28 fma2, no loads
__device__ __forceinline__ void mac_h(const float4 w, const H7& h,
                                      u64* ai, u64* af, u64* ag, u64* ao)
{
    u64 wx = dup2(w.x), wy = dup2(w.y), wz = dup2(w.z), ww = dup2(w.w);
    u64 hv[7] = { h.A.u[0], h.A.u[1], h.B.u[0], h.B.u[1], h.C.u[0], h.C.u[1], h.D.u };
    #pragma unroll
    for (int p = 0; p < 7; p++) {
        ai[p] = fma2(hv[p], wx, ai[p]);
        af[p] = fma2(hv[p], wy, af[p]);
        ag[p] = fma2(hv[p], wz, ag[p]);
        ao[p] = fma2(hv[p], ww, ao[p]);
    }
}

// ---------------------------------------------------------------------------
// Main persistent kernel: one CTA handles 14 batch rows end-to-end.
// ---------------------------------------------------------------------------
__global__ void __launch_bounds__(256, 2)
lstm_kernel(const float* __restrict__ meta,
            const float* __restrict__ b1,
            const float* __restrict__ b2,
            const float* __restrict__ bo1,
            const float* __restrict__ Wo2,
            const float* __restrict__ bo2,
            float* __restrict__ out,
            int T_eff)
{
    __shared__ __align__(16) float h2[2][256][HS]; // double-buffered h [buf][k][row]
    __shared__ __align__(16) float xs[3][16];      // [elem][row] current x (fed-back y)
    __shared__ __align__(16) float zb[14][132];    // decoder hidden [row][j2]
    __shared__ float metas[14][8];
    __shared__ __align__(16) float wo2s[3 * 128];
    __shared__ float bo1s[128];
    __shared__ float bo2s[4];

    const int t    = threadIdx.x;
    const int row0 = blockIdx.x * R_;

    // ---- stage small tensors (row indices clamped for the partial last CTA) ----
    if (t < 112) {
        int r = t >> 3, e = t & 7;
        int g = row0 + r; if (g > B_ - 1) g = B_ - 1;
        metas[r][e] = (e < 7) ? meta[g * 7 + e] : 0.f;
    }
    if (t < 128) bo1s[t] = bo1[t];
    wo2s[t] = Wo2[t];
    if (t < 128) wo2s[256 + t] = Wo2[256 + t];
    if (t < 3)   bo2s[t] = bo2[t];
    if (t < 42) {
        int r = t / 3, o = t - 3 * (t / 3);
        int g = row0 + r; if (g > B_ - 1) g = B_ - 1;
        xs[o][r] = meta[g * 7 + o];   // x0 = metadata[:, :3]
    }
    __syncthreads();

    // ---- encoder layer 1: enc1 -> h2[1][t][r] ----
    {
        float a[R_];
        float bb = b1[t];
        #pragma unroll
        for (int r = 0; r < R_; r++) a[r] = bb;
        #pragma unroll
        for (int k = 0; k < 7; k++) {
            float w = g_W1T[k * 256 + t];
            #pragma unroll
            for (int r = 0; r < R_; r++) a[r] += metas[r][k] * w;
        }
        #pragma unroll
        for (int r = 0; r < R_; r++) h2[1][t][r] = fmaxf(a[r], 0.f);
    }
    __syncthreads();

    // ---- encoder layer 2: h0 -> h2[0], c0 in regs ----
    u64 c2[7];
    {
        u64 ha[7], ca[7];
        u64 bh = dup2(b2[t]), bc = dup2(b2[256 + t]);
        #pragma unroll
        for (int p = 0; p < 7; p++) { ha[p] = bh; ca[p] = bc; }
        const float* hrow = &h2[1][0][0];
        #pragma unroll 2
        for (int k = 0; k < 256; k++) {
            u64 wh = dup2(g_W2T[k * 512 + t]);
            u64 wc = dup2(g_W2T[k * 512 + 256 + t]);
            H7 h; loadh(h, hrow + k * HS);
            u64 hv[7] = { h.A.u[0], h.A.u[1], h.B.u[0], h.B.u[1],
                          h.C.u[0], h.C.u[1], h.D.u };
            #pragma unroll
            for (int p = 0; p < 7; p++) {
                ha[p] = fma2(hv[p], wh, ha[p]);
                ca[p] = fma2(hv[p], wc, ca[p]);
            }
        }
        #pragma unroll
        for (int p = 0; p < 7; p++) {
            float2 hv = unpk(ha[p]);
            float2 cv = unpk(ca[p]);
            h2[0][t][2 * p]     = fmaxf(hv.x, 0.f);
            h2[0][t][2 * p + 1] = fmaxf(hv.y, 0.f);
            c2[p] = pk(fmaxf(cv.x, 0.f), fmaxf(cv.y, 0.f));
        }
    }
    __syncthreads();

    const int j2 = t & 127;
    const int hi = t >> 7;
    float* outp = out + (long)row0 * (T_eff * 3);
    int cur = 0;

    // =====================  LSTM scan  =====================
    for (int step = 0; step < T_eff; step++) {
        const int nxt = cur ^ 1;

        // ---- gate accumulation: gates[j] = bias + x.Wih + h.Whh ----
        u64 ai[7], af[7], ag[7], ao[7];
        {
            float4 bb = g_packBias[t];
            u64 bi = dup2(bb.x), bf = dup2(bb.y), bg = dup2(bb.z), bo = dup2(bb.w);
            #pragma unroll
            for (int p = 0; p < 7; p++) { ai[p] = bi; af[p] = bf; ag[p] = bg; ao[p] = bo; }
            #pragma unroll
            for (int e = 0; e < 3; e++) {
                float4 we = g_packWih[e * 256 + t];
                u64 wx = dup2(we.x), wy = dup2(we.y), wz = dup2(we.z), ww = dup2(we.w);
                #pragma unroll
                for (int p = 0; p < 7; p++) {
                    u64 xp = *reinterpret_cast<const u64*>(&xs[e][2 * p]);
                    ai[p] = fma2(xp, wx, ai[p]);
                    af[p] = fma2(xp, wy, af[p]);
                    ag[p] = fma2(xp, wz, ag[p]);
                    ao[p] = fma2(xp, ww, ao[p]);
                }
            }
        }
        {
            // Weights: 8-deep LDG ping-pong (a/b groups).
            // h operands: 2-slot register ping-pong — the LDS for slice k+1 are
            // in flight while slice k's 28-FFMA2 chain executes.
            const float4* wp   = g_packWhh + t;
            const float*  hrow = &h2[cur][0][0];
            H7 hh0, hh1;
            loadh(hh0, hrow);                       // h(k=0)
            float4 a0 = wp[0 * 256], a1 = wp[1 * 256],
                   a2 = wp[2 * 256], a3 = wp[3 * 256];
            #pragma unroll 1
            for (int kb = 0; kb < 248; kb += 8) {
                float4 b0 = wp[(kb + 4) * 256], b1 = wp[(kb + 5) * 256],
                       b2w = wp[(kb + 6) * 256], b3 = wp[(kb + 7) * 256];
                const float* hb = hrow + kb * HS;
                loadh(hh1, hb + 1 * HS);  mac_h(a0, hh0, ai, af, ag, ao);
                loadh(hh0, hb + 2 * HS);  mac_h(a1, hh1, ai, af, ag, ao);
                loadh(hh1, hb + 3 * HS);  mac_h(a2, hh0, ai, af, ag, ao);
                loadh(hh0, hb + 4 * HS);  mac_h(a3, hh1, ai, af, ag, ao);
                a0 = wp[(kb + 8) * 256];  a1 = wp[(kb + 9) * 256];
                a2 = wp[(kb + 10) * 256]; a3 = wp[(kb + 11) * 256];
                loadh(hh1, hb + 5 * HS);  mac_h(b0,  hh0, ai, af, ag, ao);
                loadh(hh0, hb + 6 * HS);  mac_h(b1,  hh1, ai, af, ag, ao);
                loadh(hh1, hb + 7 * HS);  mac_h(b2w, hh0, ai, af, ag, ao);
                loadh(hh0, hb + 8 * HS);  mac_h(b3,  hh1, ai, af, ag, ao);
            }
            {   // epilogue: k = 248..255 (hh0 holds h(248); a holds w(248..251))
                float4 b0 = wp[252 * 256], b1 = wp[253 * 256],
                       b2w = wp[254 * 256], b3 = wp[255 * 256];
                const float* hb = hrow + 248 * HS;
                loadh(hh1, hb + 1 * HS);  mac_h(a0, hh0, ai, af, ag, ao);
                loadh(hh0, hb + 2 * HS);  mac_h(a1, hh1, ai, af, ag, ao);
                loadh(hh1, hb + 3 * HS);  mac_h(a2, hh0, ai, af, ag, ao);
                loadh(hh0, hb + 4 * HS);  mac_h(a3, hh1, ai, af, ag, ao);
                loadh(hh1, hb + 5 * HS);  mac_h(b0,  hh0, ai, af, ag, ao);
                loadh(hh0, hb + 6 * HS);  mac_h(b1,  hh1, ai, af, ag, ao);
                loadh(hh1, hb + 7 * HS);  mac_h(b2w, hh0, ai, af, ag, ao);
                                          mac_h(b3,  hh1, ai, af, ag, ao);
            }
        }

        // ---- elementwise LSTM cell update: write new h into the OTHER buffer ----
        {
            float hn[R_];
            #pragma unroll
            for (int p = 0; p < 7; p++) {
                float2 iv = unpk(ai[p]), fv = unpk(af[p]);
                float2 gv = unpk(ag[p]), ov = unpk(ao[p]);
                float2 cv = unpk(c2[p]);
                float c0n = sigmoidf_(fv.x) * cv.x + sigmoidf_(iv.x) * tanhf_(gv.x);
                float c1n = sigmoidf_(fv.y) * cv.y + sigmoidf_(iv.y) * tanhf_(gv.y);
                hn[2 * p]     = sigmoidf_(ov.x) * tanhf_(c0n);
                hn[2 * p + 1] = sigmoidf_(ov.y) * tanhf_(c1n);
                c2[p] = pk(c0n, c1n);
            }
            float* hrow = &h2[nxt][t][0];
            *reinterpret_cast<float4*>(hrow + 0)  = make_float4(hn[0], hn[1], hn[2], hn[3]);
            *reinterpret_cast<float4*>(hrow + 4)  = make_float4(hn[4], hn[5], hn[6], hn[7]);
            *reinterpret_cast<float4*>(hrow + 8)  = make_float4(hn[8], hn[9], hn[10], hn[11]);
            *reinterpret_cast<float2*>(hrow + 12) = make_float2(hn[12], hn[13]);
        }
        __syncthreads();   // S1: new h visible; everyone done reading xs

        // ---- decoder layer 1 (ALL 256 threads): z = relu(h . Wo1^T + bo1) ----
        {
            const float* wo    = g_Wo1T + j2;
            const float* hrow2 = &h2[nxt][0][0];
            u64 bz = dup2(bo1s[j2]);
            float wv[8];
            #pragma unroll
            for (int i = 0; i < 8; i++) wv[i] = wo[i * 128];
            if (hi == 0) {
                u64 z0 = bz, z1 = bz, z2 = bz, z3 = bz;           // rows 0..7
                #pragma unroll 1
                for (int kb = 0; kb < 248; kb += 8) {
                    float nv[8];
                    #pragma unroll
                    for (int i = 0; i < 8; i++) nv[i] = wo[(kb + 8 + i) * 128];
                    #pragma unroll
                    for (int i = 0; i < 8; i++) {
                        u64 wd = dup2(wv[i]);
                        const float* hb = hrow2 + (kb + i) * HS;
                        F4 A, Bv;
                        A.f  = *reinterpret_cast<const float4*>(hb);
                        Bv.f = *reinterpret_cast<const float4*>(hb + 4);
                        z0 = fma2(A.u[0],  wd, z0);
                        z1 = fma2(A.u[1],  wd, z1);
                        z2 = fma2(Bv.u[0], wd, z2);
                        z3 = fma2(Bv.u[1], wd, z3);
                    }
                    #pragma unroll
                    for (int i = 0; i < 8; i++) wv[i] = nv[i];
                }
                #pragma unroll
                for (int i = 0; i < 8; i++) {
                    u64 wd = dup2(wv[i]);
                    const float* hb = hrow2 + (248 + i) * HS;
                    F4 A, Bv;
                    A.f  = *reinterpret_cast<const float4*>(hb);
                    Bv.f = *reinterpret_cast<const float4*>(hb + 4);
                    z0 = fma2(A.u[0],  wd, z0);
                    z1 = fma2(A.u[1],  wd, z1);
                    z2 = fma2(Bv.u[0], wd, z2);
                    z3 = fma2(Bv.u[1], wd, z3);
                }
                float2 v;
                v = unpk(z0); zb[0][j2] = fmaxf(v.x, 0.f); zb[1][j2] = fmaxf(v.y, 0.f);
                v = unpk(z1); zb[2][j2] = fmaxf(v.x, 0.f); zb[3][j2] = fmaxf(v.y, 0.f);
                v = unpk(z2); zb[4][j2] = fmaxf(v.x, 0.f); zb[5][j2] = fmaxf(v.y, 0.f);
                v = unpk(z3); zb[6][j2] = fmaxf(v.x, 0.f); zb[7][j2] = fmaxf(v.y, 0.f);
            } else {
                u64 z0 = bz, z1 = bz, z2 = bz;                    // rows 8..13
                #pragma unroll 1
                for (int kb = 0; kb < 248; kb += 8) {
                    float nv[8];
                    #pragma unroll
                    for (int i = 0; i < 8; i++) nv[i] = wo[(kb + 8 + i) * 128];
                    #pragma unroll
                    for (int i = 0; i < 8; i++) {
                        u64 wd = dup2(wv[i]);
                        const float* hb = hrow2 + (kb + i) * HS;
                        F4 Cv; F2 Dv;
                        Cv.f = *reinterpret_cast<const float4*>(hb + 8);
                        Dv.f = *reinterpret_cast<const float2*>(hb + 12);
                        z0 = fma2(Cv.u[0], wd, z0);
                        z1 = fma2(Cv.u[1], wd, z1);
                        z2 = fma2(Dv.u,    wd, z2);
                    }
                    #pragma unroll
                    for (int i = 0; i < 8; i++) wv[i] = nv[i];
                }
                #pragma unroll
                for (int i = 0; i < 8; i++) {
                    u64 wd = dup2(wv[i]);
                    const float* hb = hrow2 + (248 + i) * HS;
                    F4 Cv; F2 Dv;
                    Cv.f = *reinterpret_cast<const float4*>(hb + 8);
                    Dv.f = *reinterpret_cast<const float2*>(hb + 12);
                    z0 = fma2(Cv.u[0], wd, z0);
                    z1 = fma2(Cv.u[1], wd, z1);
                    z2 = fma2(Dv.u,    wd, z2);
                }
                float2 v;
                v = unpk(z0); zb[ 8][j2] = fmaxf(v.x, 0.f); zb[ 9][j2] = fmaxf(v.y, 0.f);
                v = unpk(z1); zb[10][j2] = fmaxf(v.x, 0.f); zb[11][j2] = fmaxf(v.y, 0.f);
                v = unpk(z2); zb[12][j2] = fmaxf(v.x, 0.f); zb[13][j2] = fmaxf(v.y, 0.f);
            }
        }
        __syncthreads();   // S2: zb ready

        // ---- decoder layer 2: y = z . Wo2^T + bo2 ; feed back as next x ----
        if (t < 42) {
            int r = t / 3, o = t - 3 * (t / 3);
            const float* zr = zb[r];
            const float* w2 = &wo2s[o * 128];
            float4 acc4 = make_float4(0.f, 0.f, 0.f, 0.f);
            #pragma unroll 8
            for (int j = 0; j < 128; j += 4) {
                float4 zv = *reinterpret_cast<const float4*>(zr + j);
                float4 wv2 = *reinterpret_cast<const float4*>(w2 + j);
                acc4.x += zv.x * wv2.x;
                acc4.y += zv.y * wv2.y;
                acc4.z += zv.z * wv2.z;
                acc4.w += zv.w * wv2.w;
            }
            float acc = bo2s[o] + ((acc4.x + acc4.y) + (acc4.z + acc4.w));
            if (row0 + r < B_) outp[r * (T_eff * 3) + step * 3 + o] = acc;
            xs[o][r] = acc;
        }
        __syncthreads();   // S3: xs ready for next step

        cur = nxt;
    }
}

// ---------------------------------------------------------------------------
// Launch
// ---------------------------------------------------------------------------
extern "C" void kernel_launch(void* const* d_in, const int* in_sizes, int n_in,
                              void* d_out, int out_size)
{
    const float* meta = (const float*)d_in[0];
    // d_in[1] = target_seq_len (encoded by the output shape)
    const float* W1   = (const float*)d_in[2];
    const float* b1   = (const float*)d_in[3];
    const float* W2   = (const float*)d_in[4];
    const float* b2   = (const float*)d_in[5];
    const float* Wih  = (const float*)d_in[6];
    const float* Whh  = (const float*)d_in[7];
    const float* bih  = (const float*)d_in[8];
    const float* bhh  = (const float*)d_in[9];
    const float* Wo1  = (const float*)d_in[10];
    const float* bo1  = (const float*)d_in[11];
    const float* Wo2  = (const float*)d_in[12];
    const float* bo2  = (const float*)d_in[13];
    float* out = (float*)d_out;

    int T_eff = out_size / (B_ * 3);   // equals target_seq_len by output shape

    prep_kernel<<<256, 256>>>(W1, W2, Wih, Whh, bih, bhh, Wo1);
    lstm_kernel<<<NCTA, 256>>>(meta, b1, b2, bo1, Wo2, bo2, out, T_eff);
}